// round 9
// baseline (speedup 1.0000x reference)
#include <cuda_runtime.h>
#include <cuda_bf16.h>
#include <cstdint>

#define NBL 4096          // B*L
#define DK  256           // MMA-covered K extent (index 256 handled exactly in fp32)
#define OD  64

// ---------------- device scratch (no allocs allowed) ----------------
__device__ __align__(16) __nv_bfloat16 g_x1h[NBL*DK], g_x1l[NBL*DK];
__device__ __align__(16) __nv_bfloat16 g_x2h[NBL*DK], g_x2l[NBL*DK];
__device__ __align__(16) __nv_bfloat16 g_Uh[(size_t)OD*DK*DK], g_Ul[(size_t)OD*DK*DK];
__device__ __align__(16) __nv_bfloat16 g_Th[(size_t)NBL*OD*DK], g_Tl[(size_t)NBL*OD*DK];
__device__ float g_t256[NBL*OD];

// ---------------- helpers (baseline sm_90 ISA only: no tcgen05) ----------------
__device__ __forceinline__ uint32_t s2u(const void* p) {
    uint32_t a;
    asm("{ .reg .u64 t; cvta.to.shared.u64 t, %1; cvt.u32.u64 %0, t; }" : "=r"(a) : "l"(p));
    return a;
}
__device__ __forceinline__ void cp16(uint32_t s, const void* g) {
    asm volatile("cp.async.cg.shared.global [%0], [%1], 16;" :: "r"(s), "l"(g));
}
__device__ __forceinline__ void cp_commit() {
    asm volatile("cp.async.commit_group;");
}
template<int N> __device__ __forceinline__ void cp_wait() {
    asm volatile("cp.async.wait_group %0;" :: "n"(N));
}
__device__ __forceinline__ void ldsm4(uint32_t r[4], uint32_t addr) {
    asm volatile("ldmatrix.sync.aligned.m8n8.x4.shared.b16 {%0,%1,%2,%3}, [%4];"
        : "=r"(r[0]), "=r"(r[1]), "=r"(r[2]), "=r"(r[3]) : "r"(addr));
}
__device__ __forceinline__ void mma16(float c[4], const uint32_t a[4], uint32_t b0, uint32_t b1) {
    asm volatile("mma.sync.aligned.m16n8k16.row.col.f32.bf16.bf16.f32 "
        "{%0,%1,%2,%3}, {%4,%5,%6,%7}, {%8,%9}, {%0,%1,%2,%3};"
        : "+f"(c[0]), "+f"(c[1]), "+f"(c[2]), "+f"(c[3])
        : "r"(a[0]), "r"(a[1]), "r"(a[2]), "r"(a[3]), "r"(b0), "r"(b1));
}

// ---------------- preprocessing ----------------
__global__ __launch_bounds__(256) void x1split(const float* __restrict__ s) {
    int i = blockIdx.x * 256 + threadIdx.x;
    float x = s[i];
    __nv_bfloat16 h = __float2bfloat16(x);
    g_x1h[i] = h; g_x1l[i] = __float2bfloat16(x - __bfloat162float(h));
}
__global__ __launch_bounds__(256) void x2split(const float* __restrict__ s) {
    int i = blockIdx.x * 256 + threadIdx.x;
    float x = s[i];
    __nv_bfloat16 h = __float2bfloat16(x);
    g_x2h[i] = h; g_x2l[i] = __float2bfloat16(x - __bfloat162float(h));
}
__global__ __launch_bounds__(256) void usplit(const float* __restrict__ U) {
    size_t idx = (size_t)blockIdx.x * 256 + threadIdx.x;   // 64*256*256
    int o = (int)(idx >> 16), r = (int)(idx & 65535), i = r >> 8, j = r & 255;
    float x = U[((size_t)o * 257 + i) * 257 + j];
    __nv_bfloat16 h = __float2bfloat16(x);
    g_Uh[idx] = h; g_Ul[idx] = __float2bfloat16(x - __bfloat162float(h));
}

// t256[bl,o] = sum_j U[o,256,j]*x1a[bl,j] + U[o,256,256]  (exact fp32)
__global__ __launch_bounds__(256) void t256_k(const float* __restrict__ x1,
                                              const float* __restrict__ U) {
    extern __shared__ char sm[];
    float* Us  = (float*)sm;             // 64 x 261 (261%32=5 -> conflict-free)
    float* x1s = (float*)sm + 64 * 261;  // 4 x 256
    const int bl0 = blockIdx.x * 4, tid = threadIdx.x;

    for (int e = tid; e < 64 * 257; e += 256) {
        int o = e / 257, j = e - o * 257;
        Us[o * 261 + j] = U[((size_t)o * 257 + 256) * 257 + j];
    }
    for (int e = tid; e < 4 * 256; e += 256)
        x1s[e] = x1[(size_t)(bl0 + (e >> 8)) * 256 + (e & 255)];
    __syncthreads();

    const int blq = tid >> 6, o = tid & 63;
    const float* ur = Us + o * 261;
    const float* xr = x1s + blq * 256;
    float p[8];
    #pragma unroll
    for (int u = 0; u < 8; u++) p[u] = 0.f;
    #pragma unroll 4
    for (int j = 0; j < 256; j += 8)
        #pragma unroll
        for (int u = 0; u < 8; u++) p[u] = fmaf(xr[j + u], ur[j + u], p[u]);
    float acc = ur[256];
    #pragma unroll
    for (int u = 0; u < 8; u++) acc += p[u];
    g_t256[(size_t)(bl0 + blq) * 64 + o] = acc;
}

// ================= K1: CTA 128(bl) x 128(i), K=256 =================
// smem: ub 512B | A0 (AH 10240 | AL 10240) | B0 (BH|BL 20480) | A1 | B1
#define K1_A0   512u
#define K1_B0   20992u
#define K1_A1   41472u
#define K1_B1   61952u
#define K1_SMEM 82432u    // 2 CTAs/SM

__device__ __forceinline__ void k1_copy(uint32_t bufA, uint32_t bufB,
        const __nv_bfloat16* Ah, const __nv_bfloat16* Al,
        const __nv_bfloat16* Bh, const __nv_bfloat16* Bl, int k0) {
    const int tid = threadIdx.x;
    #pragma unroll
    for (int u = tid; u < 512; u += 256) {   // 128 rows x 4 16B-units
        int row = u >> 2, c = u & 3;
        uint32_t off = (uint32_t)(row * 80 + c * 16);
        size_t go = (size_t)row * DK + k0 + c * 8;
        cp16(bufA + off, Ah + go);
        cp16(bufA + 10240u + off, Al + go);
        cp16(bufB + off, Bh + go);
        cp16(bufB + 10240u + off, Bl + go);
    }
    cp_commit();
}

__device__ __forceinline__ void k1_compute(uint32_t bufA, uint32_t bufB,
        int lane, int wm, int wn, float c[2][8][4]) {
    uint32_t rowA = bufA + (uint32_t)((wm * 32 + (lane & 15)) * 80 + ((lane >> 4) * 16));
    uint32_t rowB = bufB + (uint32_t)((wn * 64 + (lane & 15)) * 80 + ((lane >> 4) * 16));
    #pragma unroll
    for (int ks = 0; ks < 2; ks++) {
        uint32_t aH[2][4], aL[2][4];
        #pragma unroll
        for (int t = 0; t < 2; t++) {
            ldsm4(aH[t], rowA + t * 1280 + ks * 32);
            ldsm4(aL[t], rowA + 10240u + t * 1280 + ks * 32);
        }
        #pragma unroll
        for (int nh = 0; nh < 2; nh++) {     // stream B in 32-n halves (reg cap)
            uint32_t bH[2][4], bL[2][4];
            #pragma unroll
            for (int g = 0; g < 2; g++) {
                ldsm4(bH[g], rowB + nh * 2560 + g * 1280 + ks * 32);
                ldsm4(bL[g], rowB + 10240u + nh * 2560 + g * 1280 + ks * 32);
            }
            #pragma unroll
            for (int t = 0; t < 2; t++)
                #pragma unroll
                for (int g = 0; g < 2; g++)
                    #pragma unroll
                    for (int h = 0; h < 2; h++) {
                        float* acc = c[t][nh * 4 + g * 2 + h];
                        mma16(acc, aH[t], bH[g][h], bH[g][h + 2]);
                        mma16(acc, aH[t], bL[g][h], bL[g][h + 2]);
                        mma16(acc, aL[t], bH[g][h], bH[g][h + 2]);
                    }
        }
    }
}

__global__ __launch_bounds__(256, 2) void k1_mm(const float* __restrict__ U) {
    extern __shared__ char sm[];
    uint32_t sb = s2u(sm);
    const int tid = threadIdx.x, lane = tid & 31, wid = tid >> 5;
    const int wm = wid >> 1, wn = wid & 1;
    const int bl0 = blockIdx.x * 128, o = blockIdx.y, i0 = blockIdx.z * 128;

    float* ub = (float*)sm;   // bias col U[o, i0+n, 256], 128 entries
    if (tid < 128) ub[tid] = U[((size_t)o * 257 + i0 + tid) * 257 + 256];

    const __nv_bfloat16* Ah = g_x1h + (size_t)bl0 * DK;
    const __nv_bfloat16* Al = g_x1l + (size_t)bl0 * DK;
    const __nv_bfloat16* Bh = g_Uh + (size_t)o * DK * DK + (size_t)i0 * DK;
    const __nv_bfloat16* Bl = g_Ul + (size_t)o * DK * DK + (size_t)i0 * DK;

    float c[2][8][4];
    #pragma unroll
    for (int t = 0; t < 2; t++)
        #pragma unroll
        for (int q = 0; q < 8; q++)
            #pragma unroll
            for (int e = 0; e < 4; e++) c[t][q][e] = 0.f;

    k1_copy(sb + K1_A0, sb + K1_B0, Ah, Al, Bh, Bl, 0);
    const uint32_t ab[2] = { sb + K1_A0, sb + K1_A1 };
    const uint32_t bb[2] = { sb + K1_B0, sb + K1_B1 };
    #pragma unroll 1
    for (int kc = 0; kc < 8; kc++) {
        if (kc < 7) {
            k1_copy(ab[(kc + 1) & 1], bb[(kc + 1) & 1], Ah, Al, Bh, Bl, (kc + 1) * 32);
            cp_wait<1>();
        } else {
            cp_wait<0>();
        }
        __syncthreads();
        k1_compute(ab[kc & 1], bb[kc & 1], lane, wm, wn, c);
        __syncthreads();
    }

    const int mr = wm * 32 + (lane >> 2);
    #pragma unroll
    for (int t = 0; t < 2; t++)
        #pragma unroll
        for (int q = 0; q < 8; q++) {
            int noff = (q >> 2) * 32 + ((q >> 1) & 1) * 16 + (q & 1) * 8;
            int n = wn * 64 + noff + (lane & 3) * 2;
            float b0f = ub[n], b1f = ub[n + 1];
            #pragma unroll
            for (int h = 0; h < 2; h++) {
                int m = bl0 + mr + t * 16 + h * 8;
                float v0 = c[t][q][h * 2 + 0] + b0f;
                float v1 = c[t][q][h * 2 + 1] + b1f;
                __nv_bfloat16 h0 = __float2bfloat16(v0);
                __nv_bfloat16 h1 = __float2bfloat16(v1);
                __nv_bfloat162 ph; ph.x = h0; ph.y = h1;
                __nv_bfloat162 pl;
                pl.x = __float2bfloat16(v0 - __bfloat162float(h0));
                pl.y = __float2bfloat16(v1 - __bfloat162float(h1));
                size_t base = ((size_t)m * OD + o) * DK + i0 + n;
                *reinterpret_cast<__nv_bfloat162*>(g_Th + base) = ph;
                *reinterpret_cast<__nv_bfloat162*>(g_Tl + base) = pl;
            }
        }
}

// ================= K2: CTA 256(m) x 64(o), K=256 =================
// smem: t2 256B | A0 (AH 20480 | AL 20480) | A1 | B0 (BH 5120 | BL 5120) | B1
#define K2_A0   256u
#define K2_A1   41216u
#define K2_B0   82176u
#define K2_B1   92416u
#define K2_SMEM 102656u   // 2 CTAs/SM

__device__ __forceinline__ void k2_copy(uint32_t bufA, uint32_t bufB,
        const __nv_bfloat16* Ah, const __nv_bfloat16* Al,
        const __nv_bfloat16* Bh, const __nv_bfloat16* Bl, int k0) {
    const int tid = threadIdx.x;
    #pragma unroll
    for (int u = tid; u < 1024; u += 256) {  // A: 256 rows x 4 units
        int row = u >> 2, c = u & 3;
        uint32_t off = (uint32_t)(row * 80 + c * 16);
        size_t go = (size_t)row * DK + k0 + c * 8;
        cp16(bufA + off, Ah + go);
        cp16(bufA + 20480u + off, Al + go);
    }
    {                                         // B: 64 rows x 4 units = 256
        int row = tid >> 2, c = tid & 3;
        uint32_t off = (uint32_t)(row * 80 + c * 16);
        size_t go = (size_t)row * DK + k0 + c * 8;
        cp16(bufB + off, Bh + go);
        cp16(bufB + 5120u + off, Bl + go);
    }
    cp_commit();
}

__device__ __forceinline__ void k2_compute(uint32_t bufA, uint32_t bufB,
        int lane, int wm, int wn, float c[4][4][4]) {
    uint32_t rowA = bufA + (uint32_t)((wm * 64 + (lane & 15)) * 80 + ((lane >> 4) * 16));
    uint32_t rowB = bufB + (uint32_t)((wn * 32 + (lane & 15)) * 80 + ((lane >> 4) * 16));
    #pragma unroll
    for (int ks = 0; ks < 2; ks++) {
        uint32_t bH[2][4], bL[2][4];
        #pragma unroll
        for (int g = 0; g < 2; g++) {
            ldsm4(bH[g], rowB + g * 1280 + ks * 32);
            ldsm4(bL[g], rowB + 5120u + g * 1280 + ks * 32);
        }
        #pragma unroll
        for (int mt = 0; mt < 4; mt++) {     // stream A in 16-m tiles (reg cap)
            uint32_t aH[4], aL[4];
            ldsm4(aH, rowA + mt * 1280 + ks * 32);
            ldsm4(aL, rowA + 20480u + mt * 1280 + ks * 32);
            #pragma unroll
            for (int g = 0; g < 2; g++)
                #pragma unroll
                for (int h = 0; h < 2; h++) {
                    float* acc = c[mt][g * 2 + h];
                    mma16(acc, aH, bH[g][h], bH[g][h + 2]);
                    mma16(acc, aH, bL[g][h], bL[g][h + 2]);
                    mma16(acc, aL, bH[g][h], bH[g][h + 2]);
                }
        }
    }
}

__global__ __launch_bounds__(256, 2) void k2_mm(float* __restrict__ out) {
    extern __shared__ char sm[];
    uint32_t sb = s2u(sm);
    const int tid = threadIdx.x, lane = tid & 31, wid = tid >> 5;
    const int wm = wid >> 1, wn = wid & 1;
    const int bl = blockIdx.x, m0 = blockIdx.y * 256, b = bl >> 9;

    float* t2 = (float*)sm;   // T[bl,o,256] broadcast (x2a[m,256]==1)
    if (tid < 64) t2[tid] = g_t256[(size_t)bl * OD + tid];

    const __nv_bfloat16* Ah = g_x2h + (size_t)(b * 512 + m0) * DK;
    const __nv_bfloat16* Al = g_x2l + (size_t)(b * 512 + m0) * DK;
    const __nv_bfloat16* Bh = g_Th + (size_t)bl * OD * DK;
    const __nv_bfloat16* Bl = g_Tl + (size_t)bl * OD * DK;

    float c[4][4][4];
    #pragma unroll
    for (int mt = 0; mt < 4; mt++)
        #pragma unroll
        for (int q = 0; q < 4; q++)
            #pragma unroll
            for (int e = 0; e < 4; e++) c[mt][q][e] = 0.f;

    k2_copy(sb + K2_A0, sb + K2_B0, Ah, Al, Bh, Bl, 0);
    const uint32_t ab[2] = { sb + K2_A0, sb + K2_A1 };
    const uint32_t bb[2] = { sb + K2_B0, sb + K2_B1 };
    #pragma unroll 1
    for (int kc = 0; kc < 8; kc++) {
        if (kc < 7) {
            k2_copy(ab[(kc + 1) & 1], bb[(kc + 1) & 1], Ah, Al, Bh, Bl, (kc + 1) * 32);
            cp_wait<1>();
        } else {
            cp_wait<0>();
        }
        __syncthreads();
        k2_compute(ab[kc & 1], bb[kc & 1], lane, wm, wn, c);
        __syncthreads();
    }

    const int mr = wm * 64 + (lane >> 2);
    #pragma unroll
    for (int mt = 0; mt < 4; mt++)
        #pragma unroll
        for (int q = 0; q < 4; q++) {
            int n = wn * 32 + q * 8 + (lane & 3) * 2;
            float b0f = t2[n], b1f = t2[n + 1];
            #pragma unroll
            for (int h = 0; h < 2; h++) {
                int m = m0 + mr + mt * 16 + h * 8;
                float2 v;
                v.x = c[mt][q][h * 2 + 0] + b0f;
                v.y = c[mt][q][h * 2 + 1] + b1f;
                *reinterpret_cast<float2*>(out + ((size_t)bl * 512 + m) * OD + n) = v;
            }
        }
}

// ---------------- launch ----------------
extern "C" void kernel_launch(void* const* d_in, const int* in_sizes, int n_in,
                              void* d_out, int out_size) {
    const float* x1 = (const float*)d_in[0];   // (8,512,1,256)
    const float* x2 = (const float*)d_in[1];   // (8,1,512,256)
    const float* U  = (const float*)d_in[2];   // (64,257,257)
    float* out = (float*)d_out;                // (8,512,512,64)

    cudaFuncSetAttribute(t256_k, cudaFuncAttributeMaxDynamicSharedMemorySize, 70912);
    cudaFuncSetAttribute(k1_mm, cudaFuncAttributeMaxDynamicSharedMemorySize, (int)K1_SMEM);
    cudaFuncSetAttribute(k2_mm, cudaFuncAttributeMaxDynamicSharedMemorySize, (int)K2_SMEM);

    x1split<<<4096, 256>>>(x1);
    x2split<<<4096, 256>>>(x2);
    usplit<<<16384, 256>>>(U);
    t256_k<<<1024, 256, 70912>>>(x1, U);
    k1_mm<<<dim3(32, 64, 2), 256, K1_SMEM>>>(U);
    k2_mm<<<dim3(4096, 2), 256, K2_SMEM>>>(out);
}